// round 3
// baseline (speedup 1.0000x reference)
#include <cuda_runtime.h>

#define BB 2
#define NN 150000
#define CC 64
#define DD 128
#define D3 (DD*DD*DD)
#define PP (BB*NN)                     // 300000 total points
#define CHUNK 2048
#define NCHUNKS ((PP + CHUNK - 1) / CHUNK)   // 147
#define NCELLS (NCHUNKS * 27)                // 3969
#define NW 16                          // warps per conv block
#define STATS_BLOCKS 592
#define BN_EPS 1e-4f

// ---------------- static device scratch (no allocations allowed) ----------------
__device__ int    g_lut[BB * D3];            // voxel -> local point idx, -1 empty
__device__ int    g_cnt[NCELLS];             // entries per (chunk, tap) cell
__device__ int    g_dst[NCELLS * CHUNK];     // dst point (global, 0..PP)
__device__ int    g_src[NCELLS * CHUNK];     // src point (global, 0..PP)
__device__ float4 g_wt2[4 * 27 * 1024];      // W transposed: [conv][tap][ci/4][oc] -> float4 over 4 ci
__device__ float  g_h[PP * CC];              // bnrelu output
__device__ float  g_c[PP * CC];              // conv scratch output
__device__ float  g_x[PP * CC];              // residual state x1
__device__ float  g_ps [STATS_BLOCKS * CC];  // partial sums
__device__ float  g_pss[STATS_BLOCKS * CC];  // partial sumsq
__device__ __align__(16) float g_scale[CC];
__device__ __align__(16) float g_shift[CC];

// buffer selectors: 0 = external pointer, 1 = g_h, 2 = g_c, 3 = g_x
__device__ __forceinline__ const float* rbuf(int sel, const float* ext) {
    if (sel == 1) return g_h;
    if (sel == 2) return g_c;
    if (sel == 3) return g_x;
    return ext;
}
__device__ __forceinline__ float* wbuf(int sel, float* ext) {
    if (sel == 1) return g_h;
    if (sel == 2) return g_c;
    if (sel == 3) return g_x;
    return ext;
}

// ---------------- clear LUT + counters (launch-only path; capture-safe) ----------------
__global__ void clear_kernel() {
    int i = blockIdx.x * blockDim.x + threadIdx.x;
    if (i < BB * D3) g_lut[i] = -1;
    if (i < NCELLS)  g_cnt[i] = 0;
}

// ---------------- LUT scatter ----------------
__global__ void scatter_kernel(const int* __restrict__ pos) {
    int p = blockIdx.x * blockDim.x + threadIdx.x;
    if (p >= PP) return;
    int b = p / NN;
    int i = p - b * NN;
    const int* pp = pos + (size_t)p * 3;
    int code = (pp[0] * DD + pp[1]) * DD + pp[2];
    g_lut[b * D3 + code] = i;
}

// ---------------- build (chunk, tap)-bucketed rule lists ----------------
__global__ void build_kernel(const int* __restrict__ pos) {
    int p = blockIdx.x * blockDim.x + threadIdx.x;
    if (p >= PP) return;
    int b = p / NN;
    const int* pp = pos + (size_t)p * 3;
    int x = pp[0], y = pp[1], z = pp[2];
    int chunk = p >> 11;  // /2048
    const int* lut = g_lut + b * D3;
#pragma unroll
    for (int k = 0; k < 27; k++) {
        int dx = k / 9 - 1, dy = (k / 3) % 3 - 1, dz = k % 3 - 1;
        int nx = x + dx, ny = y + dy, nz = z + dz;
        if ((unsigned)nx < DD && (unsigned)ny < DD && (unsigned)nz < DD) {
            int nidx = lut[(nx * DD + ny) * DD + nz];
            if (nidx >= 0) {
                int cell = chunk * 27 + k;
                int slot = atomicAdd(&g_cnt[cell], 1);
                g_dst[cell * CHUNK + slot] = p;
                g_src[cell * CHUNK + slot] = b * NN + nidx;
            }
        }
    }
}

// ---------------- weight transpose: W[w][k][ci][oc] -> g_wt2[(w*27+k)*1024 + cb*64 + oc] ----------------
__global__ void wt2_kernel(const float* __restrict__ W) {
    int idx = blockIdx.x * blockDim.x + threadIdx.x;  // 4*27*16*64 = 110592
    if (idx >= 4 * 27 * 16 * 64) return;
    int oc = idx & 63;
    int cb = (idx >> 6) & 15;
    int kw = idx >> 10;            // conv*27 + k
    const float* src = W + (size_t)kw * 4096;
    float4 v;
    v.x = src[(4 * cb + 0) * 64 + oc];
    v.y = src[(4 * cb + 1) * 64 + oc];
    v.z = src[(4 * cb + 2) * 64 + oc];
    v.w = src[(4 * cb + 3) * 64 + oc];
    g_wt2[idx] = v;
}

// ---------------- BN stats: per-channel sum / sumsq partials ----------------
__global__ void stats_kernel(const float* __restrict__ ext, int sel) {
    const float* x = rbuf(sel, ext);
    __shared__ float ssum[256], ssq[256];
    int t = threadIdx.x;
    int ch = t & 63, grp = t >> 6;
    float s = 0.f, q = 0.f;
    for (int row = blockIdx.x * 4 + grp; row < PP; row += gridDim.x * 4) {
        float v = x[(size_t)row * 64 + ch];
        s += v; q += v * v;
    }
    ssum[t] = s; ssq[t] = q;
    __syncthreads();
    if (t < 64) {
        s = ssum[t] + ssum[t + 64] + ssum[t + 128] + ssum[t + 192];
        q = ssq[t] + ssq[t + 64] + ssq[t + 128] + ssq[t + 192];
        g_ps [blockIdx.x * 64 + t] = s;
        g_pss[blockIdx.x * 64 + t] = q;
    }
}

__global__ void finalize_kernel(const float* __restrict__ gammas, const float* __restrict__ betas, int cidx) {
    int ch = threadIdx.x;  // 64 threads
    float s = 0.f, q = 0.f;
    for (int b2 = 0; b2 < STATS_BLOCKS; b2++) {
        s += g_ps [b2 * 64 + ch];
        q += g_pss[b2 * 64 + ch];
    }
    float inv = 1.0f / (float)PP;
    float mu  = s * inv;
    float var = q * inv - mu * mu;
    float sc  = gammas[cidx * 64 + ch] * rsqrtf(var + BN_EPS);
    g_scale[ch] = sc;
    g_shift[ch] = betas[cidx * 64 + ch] - mu * sc;
}

// ---------------- fused BN + ReLU elementwise: in -> g_h ----------------
__global__ void bnrelu_kernel(const float* __restrict__ ext, int sel) {
    const float4* x = (const float4*)rbuf(sel, ext);
    float4* h = (float4*)g_h;
    int i = blockIdx.x * blockDim.x + threadIdx.x;
    if (i >= PP * 16) return;
    int cq = i & 15;
    float4 sc = ((const float4*)g_scale)[cq];
    float4 sh = ((const float4*)g_shift)[cq];
    float4 v = x[i];
    float4 r;
    r.x = fmaxf(v.x * sc.x + sh.x, 0.f);
    r.y = fmaxf(v.y * sc.y + sh.y, 0.f);
    r.z = fmaxf(v.z * sc.z + sh.z, 0.f);
    r.w = fmaxf(v.w * sc.w + sh.w, 0.f);
    h[i] = r;
}

// ---------------- sparse conv: one block per dst chunk; tap-major, smem-staged W ----------------
// Center tap (k=13) processed first: writes out = base + y (covers every point, un-poisons out).
// Other taps: out += y. All taps of a dst live in this block -> no atomics, deterministic
// (per-dst accumulation order fixed: kk order; per-entry dot order fixed).
__global__ __launch_bounds__(512) void conv_kernel(int cidx,
                                                   float* __restrict__ out_ext, int out_sel,
                                                   const float* __restrict__ base_ext, int base_sel) {
    float* out = wbuf(out_sel, out_ext);
    const float* base = (base_sel < 0) ? nullptr : rbuf(base_sel, base_ext);
    const float4* wt2 = g_wt2 + (size_t)cidx * 27 * 1024;

    __shared__ float4 Ws[1024];          // 16 KB: [cb][oc]
    __shared__ float4 Xs[NW][2][16];     // per-warp, 2 entries x 16 float4 (64 ci)
    int tid  = threadIdx.x;
    int wid  = tid >> 5;
    int lane = tid & 31;
    int li   = lane & 15;
    int half = lane >> 4;
    int chunk = blockIdx.x;
    const float4* h4 = (const float4*)g_h;

    for (int kk = 0; kk < 27; kk++) {
        int k = (kk == 0) ? 13 : (kk <= 13 ? kk - 1 : kk);
        int cell = chunk * 27 + k;
        int cnt = g_cnt[cell];
        __syncthreads();                 // Ws reads of prev tap done; RMW ordering across taps
        if (cnt == 0) continue;
        const float4* wsrc = wt2 + k * 1024;
        Ws[tid]       = wsrc[tid];
        Ws[tid + 512] = wsrc[tid + 512];
        __syncthreads();

        int off = cell * CHUNK;
        int end = off + cnt;
        for (int eb = off + wid * 2; eb < end; eb += NW * 2) {
            int e = eb + half;
            bool act = (e < end);
            int dstp = 0, srcp = 0;
            if (act) { dstp = g_dst[e]; srcp = g_src[e]; }
            if (act) Xs[wid][half][li] = h4[(size_t)srcp * 16 + li];
            __syncwarp();
            float ax = 0.f, ay = 0.f, az = 0.f, aw = 0.f;
#pragma unroll
            for (int cb = 0; cb < 16; cb++) {
                float4 xv = Xs[wid][half][cb];
                float4 w0 = Ws[cb * 64 + li];
                float4 w1 = Ws[cb * 64 + 16 + li];
                float4 w2 = Ws[cb * 64 + 32 + li];
                float4 w3 = Ws[cb * 64 + 48 + li];
                ax += xv.x * w0.x; ax += xv.y * w0.y; ax += xv.z * w0.z; ax += xv.w * w0.w;
                ay += xv.x * w1.x; ay += xv.y * w1.y; ay += xv.z * w1.z; ay += xv.w * w1.w;
                az += xv.x * w2.x; az += xv.y * w2.y; az += xv.z * w2.z; az += xv.w * w2.w;
                aw += xv.x * w3.x; aw += xv.y * w3.y; aw += xv.z * w3.z; aw += xv.w * w3.w;
            }
            if (act) {
                float* orow = out + (size_t)dstp * 64;
                if (kk == 0) {
                    if (base) {
                        const float* br = base + (size_t)dstp * 64;
                        ax += br[li]; ay += br[li + 16]; az += br[li + 32]; aw += br[li + 48];
                    }
                    orow[li]      = ax;
                    orow[li + 16] = ay;
                    orow[li + 32] = az;
                    orow[li + 48] = aw;
                } else {
                    orow[li]      += ax;
                    orow[li + 16] += ay;
                    orow[li + 32] += az;
                    orow[li + 48] += aw;
                }
            }
            __syncwarp();
        }
    }
}

// ---------------- driver (kernel launches only — capture-safe) ----------------
static void run_stage(const float* in_ext, int in_sel,
                      const float* gammas, const float* betas, int cidx,
                      float* out_ext, int out_sel,
                      const float* base_ext, int base_sel) {
    stats_kernel<<<STATS_BLOCKS, 256>>>(in_ext, in_sel);
    finalize_kernel<<<1, 64>>>(gammas, betas, cidx);
    bnrelu_kernel<<<(PP * 16 + 255) / 256, 256>>>(in_ext, in_sel);
    conv_kernel<<<NCHUNKS, 512>>>(cidx, out_ext, out_sel, base_ext, base_sel);
}

extern "C" void kernel_launch(void* const* d_in, const int* in_sizes, int n_in,
                              void* d_out, int out_size) {
    const float* feats  = (const float*)d_in[0];
    const float* Ws     = (const float*)d_in[1];
    const float* gammas = (const float*)d_in[2];
    const float* betas  = (const float*)d_in[3];
    const int*   pos    = (const int*)d_in[4];
    float* outp = (float*)d_out;

    // precompute (rebuilt every call; graph-replay safe, deterministic output)
    clear_kernel<<<(BB * D3 + 255) / 256, 256>>>();
    scatter_kernel<<<(PP + 255) / 256, 256>>>(pos);
    build_kernel<<<(PP + 255) / 256, 256>>>(pos);
    wt2_kernel<<<(4 * 27 * 16 * 64 + 255) / 256, 256>>>(Ws);

    // block 1: c = conv(bnrelu(feats), W0); x = feats + conv(bnrelu(c), W1)
    run_stage(feats,   0, gammas, betas, 0, nullptr, 2, nullptr, -1);
    run_stage(nullptr, 2, gammas, betas, 1, nullptr, 3, feats,    0);
    // block 2: c = conv(bnrelu(x), W2); out = x + conv(bnrelu(c), W3)
    run_stage(nullptr, 3, gammas, betas, 2, nullptr, 2, nullptr, -1);
    run_stage(nullptr, 2, gammas, betas, 3, outp,    0, nullptr,  3);
}

// round 5
// speedup vs baseline: 1.1381x; 1.1381x over previous
#include <cuda_runtime.h>

#define BB 2
#define NN 150000
#define CC 64
#define DD 128
#define D3 (DD*DD*DD)
#define PP (BB*NN)                     // 300000 total points
#define CHUNK 2048
#define NCHUNKS ((PP + CHUNK - 1) / CHUNK)   // 147
#define NCELLS (NCHUNKS * 27)
#define TE 128                         // entries per GEMM tile
#define STATS_BLOCKS 592
#define BN_EPS 1e-4f

// ---------------- static device scratch ----------------
__device__ int    g_lut[BB * D3];
__device__ int    g_cnt[NCELLS];
__device__ int    g_dst[NCELLS * CHUNK];
__device__ int    g_src[NCELLS * CHUNK];
__device__ float  g_c[PP * CC];
__device__ float  g_x[PP * CC];
__device__ float  g_ps [STATS_BLOCKS * CC];
__device__ float  g_pss[STATS_BLOCKS * CC];
__device__ __align__(16) float g_scale[CC];
__device__ __align__(16) float g_shift[CC];

// buffer selectors: 0 = external pointer, 2 = g_c, 3 = g_x
__device__ __forceinline__ const float* rbuf(int sel, const float* ext) {
    if (sel == 2) return g_c;
    if (sel == 3) return g_x;
    return ext;
}
__device__ __forceinline__ float* wbuf(int sel, float* ext) {
    if (sel == 2) return g_c;
    if (sel == 3) return g_x;
    return ext;
}

// ---------------- clear LUT + counters ----------------
__global__ void clear_kernel() {
    int i = blockIdx.x * blockDim.x + threadIdx.x;
    if (i < BB * D3) g_lut[i] = -1;
    if (i < NCELLS)  g_cnt[i] = 0;
}

// ---------------- LUT scatter ----------------
__global__ void scatter_kernel(const int* __restrict__ pos) {
    int p = blockIdx.x * blockDim.x + threadIdx.x;
    if (p >= PP) return;
    int b = p / NN;
    int i = p - b * NN;
    const int* pp = pos + (size_t)p * 3;
    int code = (pp[0] * DD + pp[1]) * DD + pp[2];
    g_lut[b * D3 + code] = i;
}

// ---------------- build rule lists (symmetric: probe 13 taps, emit both dirs) ----------------
__global__ void build_kernel(const int* __restrict__ pos) {
    int p = blockIdx.x * blockDim.x + threadIdx.x;
    if (p >= PP) return;
    int b = p / NN;
    const int* pp = pos + (size_t)p * 3;
    int x = pp[0], y = pp[1], z = pp[2];
    int chunk = p >> 11;
    const int* lut = g_lut + b * D3;
    // center tap (13): src = dst = p
    {
        int cell = chunk * 27 + 13;
        int slot = atomicAdd(&g_cnt[cell], 1);
        g_dst[cell * CHUNK + slot] = p;
        g_src[cell * CHUNK + slot] = p;
    }
#pragma unroll
    for (int k = 0; k < 13; k++) {
        int dx = k / 9 - 1, dy = (k / 3) % 3 - 1, dz = k % 3 - 1;
        int nx = x + dx, ny = y + dy, nz = z + dz;
        if ((unsigned)nx < DD && (unsigned)ny < DD && (unsigned)nz < DD) {
            int nidx = lut[(nx * DD + ny) * DD + nz];
            if (nidx >= 0) {
                int qg = b * NN + nidx;
                // dst p, tap k, src q
                int cell1 = chunk * 27 + k;
                int s1 = atomicAdd(&g_cnt[cell1], 1);
                g_dst[cell1 * CHUNK + s1] = p;
                g_src[cell1 * CHUNK + s1] = qg;
                // dst q, tap 26-k, src p   (OFFS[26-k] == -OFFS[k])
                int cell2 = (qg >> 11) * 27 + (26 - k);
                int s2 = atomicAdd(&g_cnt[cell2], 1);
                g_dst[cell2 * CHUNK + s2] = qg;
                g_src[cell2 * CHUNK + s2] = p;
            }
        }
    }
}

// ---------------- BN stats: per-channel sum / sumsq partials ----------------
__global__ void stats_kernel(const float* __restrict__ ext, int sel) {
    const float* x = rbuf(sel, ext);
    __shared__ float ssum[256], ssq[256];
    int t = threadIdx.x;
    int ch = t & 63, grp = t >> 6;
    float s = 0.f, q = 0.f;
    for (int row = blockIdx.x * 4 + grp; row < PP; row += gridDim.x * 4) {
        float v = x[(size_t)row * 64 + ch];
        s += v; q += v * v;
    }
    ssum[t] = s; ssq[t] = q;
    __syncthreads();
    if (t < 64) {
        s = ssum[t] + ssum[t + 64] + ssum[t + 128] + ssum[t + 192];
        q = ssq[t] + ssq[t + 64] + ssq[t + 128] + ssq[t + 192];
        g_ps [blockIdx.x * 64 + t] = s;
        g_pss[blockIdx.x * 64 + t] = q;
    }
}

__global__ void finalize_kernel(const float* __restrict__ gammas, const float* __restrict__ betas, int cidx) {
    int ch = threadIdx.x;  // 64 threads
    float s = 0.f, q = 0.f;
    for (int b2 = 0; b2 < STATS_BLOCKS; b2++) {
        s += g_ps [b2 * 64 + ch];
        q += g_pss[b2 * 64 + ch];
    }
    float inv = 1.0f / (float)PP;
    float mu  = s * inv;
    float var = q * inv - mu * mu;
    float sc  = gammas[cidx * 64 + ch] * rsqrtf(var + BN_EPS);
    g_scale[ch] = sc;
    g_shift[ch] = betas[cidx * 64 + ch] - mu * sc;
}

// ---------------- sparse conv as register-blocked GEMM ----------------
// One block per 2048-dst chunk. Per tap: stage W[k] (64x64) to smem; per 128-entry
// tile: gather bnrelu(in[src]) into Xs[ci][e] (fused BN+ReLU), then GEMM
// [128e x 64oc x 64K] with 8x4 register blocking, scatter-add to out.
// Center tap first: out = base + y (store, covers every dst). Others: out += y.
// Deterministic: all taps of a dst in this block, tap order fixed, K order fixed.
__global__ __launch_bounds__(256) void conv_kernel(int cidx, const float* __restrict__ Wg,
                                                   const float* __restrict__ in_ext, int in_sel,
                                                   float* __restrict__ out_ext, int out_sel,
                                                   const float* __restrict__ base_ext, int base_sel) {
    const float* in  = rbuf(in_sel, in_ext);
    float* out       = wbuf(out_sel, out_ext);
    const float* base = (base_sel < 0) ? nullptr : rbuf(base_sel, base_ext);
    const float4* in4 = (const float4*)in;

    __shared__ __align__(16) float Xs[64][TE];   // 32 KB  [ci][e]
    __shared__ __align__(16) float Wsm[64][64];  // 16 KB  [ci][oc]
    const float4* XsV = (const float4*)&Xs[0][0];
    const float4* WsV = (const float4*)&Wsm[0][0];

    int tid = threadIdx.x;
    int tx = tid & 15;          // oc group: oc = tx*4 .. +3
    int ty = tid >> 4;          // entry group
    int ge = tid >> 1;          // gather entry 0..127
    int part = tid & 1;         // gather half (ci 0..31 / 32..63)
    int chunk = blockIdx.x;

    const float4* sc4 = (const float4*)g_scale;
    const float4* sh4 = (const float4*)g_shift;

    for (int kk = 0; kk < 27; kk++) {
        int k = (kk == 0) ? 13 : (kk <= 13 ? kk - 1 : kk);
        int cell = chunk * 27 + k;
        int cnt = g_cnt[cell];
        if (cnt == 0) continue;

        __syncthreads();  // prev tap done with Wsm reads + global RMW ordering
        // stage W[k]: 64x64 floats = 1024 float4
        const float4* wsrc = (const float4*)(Wg + ((size_t)cidx * 27 + k) * 4096);
#pragma unroll
        for (int i = 0; i < 4; i++)
            ((float4*)&Wsm[0][0])[tid + i * 256] = wsrc[tid + i * 256];

        int off = cell * CHUNK;
        for (int t0 = 0; t0 < cnt; t0 += TE) {
            int n = min(TE, cnt - t0);
            __syncthreads();  // prev tile's GEMM done reading Xs; W staged
            // ---- gather + fused bnrelu into Xs ----
            if (ge < n) {
                int srcp = g_src[off + t0 + ge];
                const float4* row = in4 + (size_t)srcp * 16 + part * 8;
#pragma unroll
                for (int j = 0; j < 8; j++) {
                    float4 v = row[j];
                    float4 sc = sc4[part * 8 + j];
                    float4 sh = sh4[part * 8 + j];
                    int ci = part * 32 + j * 4;
                    Xs[ci + 0][ge] = fmaxf(v.x * sc.x + sh.x, 0.f);
                    Xs[ci + 1][ge] = fmaxf(v.y * sc.y + sh.y, 0.f);
                    Xs[ci + 2][ge] = fmaxf(v.z * sc.z + sh.z, 0.f);
                    Xs[ci + 3][ge] = fmaxf(v.w * sc.w + sh.w, 0.f);
                }
            }
            __syncthreads();
            // ---- GEMM: 8 entries x 4 oc per thread ----
            float acc[8][4];
#pragma unroll
            for (int r = 0; r < 8; r++)
#pragma unroll
                for (int j = 0; j < 4; j++) acc[r][j] = 0.f;
#pragma unroll
            for (int ci = 0; ci < 64; ci++) {
                float4 w  = WsV[ci * 16 + tx];
                float4 a0 = XsV[ci * 32 + ty];
                float4 a1 = XsV[ci * 32 + 16 + ty];
                float a[8] = {a0.x, a0.y, a0.z, a0.w, a1.x, a1.y, a1.z, a1.w};
                float wv[4] = {w.x, w.y, w.z, w.w};
#pragma unroll
                for (int r = 0; r < 8; r++)
#pragma unroll
                    for (int j = 0; j < 4; j++) acc[r][j] += a[r] * wv[j];
            }
            // ---- scatter(-add) epilogue ----
#pragma unroll
            for (int g = 0; g < 2; g++) {
#pragma unroll
                for (int r = 0; r < 4; r++) {
                    int e = g * 64 + ty * 4 + r;
                    if (e < n) {
                        int dstp = g_dst[off + t0 + e];
                        float4* orow = (float4*)(out + (size_t)dstp * 64) + tx;
                        float4 v = make_float4(acc[g * 4 + r][0], acc[g * 4 + r][1],
                                               acc[g * 4 + r][2], acc[g * 4 + r][3]);
                        if (kk == 0) {
                            if (base) {
                                float4 b4 = ((const float4*)(base + (size_t)dstp * 64))[tx];
                                v.x += b4.x; v.y += b4.y; v.z += b4.z; v.w += b4.w;
                            }
                            *orow = v;
                        } else {
                            float4 o = *orow;
                            o.x += v.x; o.y += v.y; o.z += v.z; o.w += v.w;
                            *orow = o;
                        }
                    }
                }
            }
        }
    }
}

// ---------------- driver (kernel launches only — capture-safe) ----------------
static void run_stage(const float* in_ext, int in_sel,
                      const float* Ws, const float* gammas, const float* betas, int cidx,
                      float* out_ext, int out_sel,
                      const float* base_ext, int base_sel) {
    stats_kernel<<<STATS_BLOCKS, 256>>>(in_ext, in_sel);
    finalize_kernel<<<1, 64>>>(gammas, betas, cidx);
    conv_kernel<<<NCHUNKS, 256>>>(cidx, Ws, in_ext, in_sel, out_ext, out_sel, base_ext, base_sel);
}

extern "C" void kernel_launch(void* const* d_in, const int* in_sizes, int n_in,
                              void* d_out, int out_size) {
    const float* feats  = (const float*)d_in[0];
    const float* Ws     = (const float*)d_in[1];
    const float* gammas = (const float*)d_in[2];
    const float* betas  = (const float*)d_in[3];
    const int*   pos    = (const int*)d_in[4];
    float* outp = (float*)d_out;

    clear_kernel<<<(BB * D3 + 255) / 256, 256>>>();
    scatter_kernel<<<(PP + 255) / 256, 256>>>(pos);
    build_kernel<<<(PP + 255) / 256, 256>>>(pos);

    // block 1: c = conv(bnrelu(feats), W0); x = feats + conv(bnrelu(c), W1)
    run_stage(feats,   0, Ws, gammas, betas, 0, nullptr, 2, nullptr, -1);
    run_stage(nullptr, 2, Ws, gammas, betas, 1, nullptr, 3, feats,    0);
    // block 2: c = conv(bnrelu(x), W2); out = x + conv(bnrelu(c), W3)
    run_stage(nullptr, 3, Ws, gammas, betas, 2, nullptr, 2, nullptr, -1);
    run_stage(nullptr, 2, Ws, gammas, betas, 3, outp,    0, nullptr,  3);
}

// round 8
// speedup vs baseline: 1.8430x; 1.6194x over previous
#include <cuda_runtime.h>
#include <cstdint>

#define BB 2
#define NN 150000
#define CC 64
#define DD 128
#define D3 (DD*DD*DD)
#define PP (BB*NN)                     // 300000 total points
#define CHUNK 1024
#define NCHUNKS ((PP + CHUNK - 1) / CHUNK)   // 294
#define NCELLS (NCHUNKS * 27)
#define TE 128                         // entries per GEMM tile
#define STATS_BLOCKS 592
#define BN_EPS 1e-4f

// ---------------- static device scratch ----------------
__device__ int    g_lut[BB * D3];
__device__ int    g_cnt[NCELLS];
__device__ int    g_dst[NCELLS * CHUNK];
__device__ int    g_src[NCELLS * CHUNK];
__device__ float  g_c[PP * CC];
__device__ float  g_x[PP * CC];
__device__ float  g_ps [STATS_BLOCKS * CC];
__device__ float  g_pss[STATS_BLOCKS * CC];
__device__ __align__(16) float g_scale[CC];
__device__ __align__(16) float g_shift[CC];

// buffer selectors: 0 = external pointer, 2 = g_c, 3 = g_x
__device__ __forceinline__ const float* rbuf(int sel, const float* ext) {
    if (sel == 2) return g_c;
    if (sel == 3) return g_x;
    return ext;
}
__device__ __forceinline__ float* wbuf(int sel, float* ext) {
    if (sel == 2) return g_c;
    if (sel == 3) return g_x;
    return ext;
}

// ---------------- packed f32x2 helpers ----------------
__device__ __forceinline__ unsigned long long splat2(float v) {
    unsigned long long r;
    unsigned int u = __float_as_uint(v);
    asm("mov.b64 %0, {%1, %1};" : "=l"(r) : "r"(u));
    return r;
}
__device__ __forceinline__ void fma2(unsigned long long& d, unsigned long long a, unsigned long long b) {
    asm("fma.rn.f32x2 %0, %1, %2, %0;" : "+l"(d) : "l"(a), "l"(b));
}
__device__ __forceinline__ float2 unpack2(unsigned long long v) {
    float2 r;
    asm("mov.b64 {%0, %1}, %2;" : "=f"(r.x), "=f"(r.y) : "l"(v));
    return r;
}

// ---------------- clear LUT + counters ----------------
__global__ void clear_kernel() {
    int i = blockIdx.x * blockDim.x + threadIdx.x;
    if (i < BB * D3) g_lut[i] = -1;
    if (i < NCELLS)  g_cnt[i] = 0;
}

// ---------------- LUT scatter ----------------
__global__ void scatter_kernel(const int* __restrict__ pos) {
    int p = blockIdx.x * blockDim.x + threadIdx.x;
    if (p >= PP) return;
    int b = p / NN;
    int i = p - b * NN;
    const int* pp = pos + (size_t)p * 3;
    int code = (pp[0] * DD + pp[1]) * DD + pp[2];
    g_lut[b * D3 + code] = i;
}

// ---------------- build rule lists (symmetric: probe 13 taps, emit both dirs) ----------------
__global__ void build_kernel(const int* __restrict__ pos) {
    int p = blockIdx.x * blockDim.x + threadIdx.x;
    if (p >= PP) return;
    int b = p / NN;
    const int* pp = pos + (size_t)p * 3;
    int x = pp[0], y = pp[1], z = pp[2];
    int chunk = p >> 10;
    const int* lut = g_lut + b * D3;
    // center tap (13): src = dst = p
    {
        int cell = chunk * 27 + 13;
        int slot = atomicAdd(&g_cnt[cell], 1);
        g_dst[cell * CHUNK + slot] = p;
        g_src[cell * CHUNK + slot] = p;
    }
#pragma unroll
    for (int k = 0; k < 13; k++) {
        int dx = k / 9 - 1, dy = (k / 3) % 3 - 1, dz = k % 3 - 1;
        int nx = x + dx, ny = y + dy, nz = z + dz;
        if ((unsigned)nx < DD && (unsigned)ny < DD && (unsigned)nz < DD) {
            int nidx = lut[(nx * DD + ny) * DD + nz];
            if (nidx >= 0) {
                int qg = b * NN + nidx;
                int cell1 = chunk * 27 + k;
                int s1 = atomicAdd(&g_cnt[cell1], 1);
                g_dst[cell1 * CHUNK + s1] = p;
                g_src[cell1 * CHUNK + s1] = qg;
                int cell2 = (qg >> 10) * 27 + (26 - k);
                int s2 = atomicAdd(&g_cnt[cell2], 1);
                g_dst[cell2 * CHUNK + s2] = qg;
                g_src[cell2 * CHUNK + s2] = p;
            }
        }
    }
}

// ---------------- BN stats: vectorized float4, per-channel sum / sumsq ----------------
__global__ void stats_kernel(const float* __restrict__ ext, int sel) {
    const float4* x4 = (const float4*)rbuf(sel, ext);
    __shared__ float4 ssum[16][16], ssq[16][16];
    int t = threadIdx.x;
    int tx = t & 15;            // channel quad: ch 4tx..4tx+3
    int ty = t >> 4;            // row group
    float4 s = make_float4(0.f, 0.f, 0.f, 0.f);
    float4 q = make_float4(0.f, 0.f, 0.f, 0.f);
#pragma unroll 4
    for (int row = blockIdx.x * 16 + ty; row < PP; row += gridDim.x * 16) {
        float4 v = x4[(size_t)row * 16 + tx];
        s.x += v.x; s.y += v.y; s.z += v.z; s.w += v.w;
        q.x += v.x * v.x; q.y += v.y * v.y; q.z += v.z * v.z; q.w += v.w * v.w;
    }
    ssum[ty][tx] = s; ssq[ty][tx] = q;
    __syncthreads();
    for (int st = 8; st > 0; st >>= 1) {
        if (ty < st) {
            float4 a = ssum[ty][tx], b = ssum[ty + st][tx];
            a.x += b.x; a.y += b.y; a.z += b.z; a.w += b.w;
            ssum[ty][tx] = a;
            float4 c = ssq[ty][tx], d = ssq[ty + st][tx];
            c.x += d.x; c.y += d.y; c.z += d.z; c.w += d.w;
            ssq[ty][tx] = c;
        }
        __syncthreads();
    }
    if (ty == 0) {
        ((float4*)g_ps )[blockIdx.x * 16 + tx] = ssum[0][tx];
        ((float4*)g_pss)[blockIdx.x * 16 + tx] = ssq[0][tx];
    }
}

__global__ void finalize_kernel(const float* __restrict__ gammas, const float* __restrict__ betas, int cidx) {
    int ch = threadIdx.x;  // 64 threads
    float s = 0.f, q = 0.f;
    for (int b2 = 0; b2 < STATS_BLOCKS; b2++) {
        s += g_ps [b2 * 64 + ch];
        q += g_pss[b2 * 64 + ch];
    }
    float inv = 1.0f / (float)PP;
    float mu  = s * inv;
    float var = q * inv - mu * mu;
    float sc  = gammas[cidx * 64 + ch] * rsqrtf(var + BN_EPS);
    g_scale[ch] = sc;
    g_shift[ch] = betas[cidx * 64 + ch] - mu * sc;
}

// ---------------- sparse conv as register-blocked GEMM (packed f32x2) ----------------
// One block per 1024-dst chunk (294 blocks -> 2/SM). Per tap: stage W[k] to smem;
// per 128-entry tile: gather bnrelu(in[src]) into Xs (fused BN+ReLU), then GEMM
// [128e x 64oc x 64K]: per thread 8 entries (4 f32x2 pairs) x 4 oc.
// Center tap first: out = base + y (store). Others: out += y. Deterministic.
__global__ __launch_bounds__(256) void conv_kernel(int cidx, const float* __restrict__ Wg,
                                                   const float* __restrict__ in_ext, int in_sel,
                                                   float* __restrict__ out_ext, int out_sel,
                                                   const float* __restrict__ base_ext, int base_sel) {
    const float* in  = rbuf(in_sel, in_ext);
    float* out       = wbuf(out_sel, out_ext);
    const float* base = (base_sel < 0) ? nullptr : rbuf(base_sel, base_ext);
    const float4* in4 = (const float4*)in;

    __shared__ __align__(16) float Xs[64][TE];   // 32 KB  [ci][e]
    __shared__ __align__(16) float Wsm[64][64];  // 16 KB  [ci][oc]
    const float4* WsV = (const float4*)&Wsm[0][0];
    const ulonglong2* XsP = (const ulonglong2*)&Xs[0][0];   // 32 ulonglong2 per row

    int tid = threadIdx.x;
    int tx = tid & 15;          // oc group: oc = tx*4 .. +3
    int ty = tid >> 4;          // entry group
    int ge = tid >> 1;          // gather entry 0..127
    int part = tid & 1;         // gather half (ci 0..31 / 32..63)
    int chunk = blockIdx.x;

    const float4* sc4 = (const float4*)g_scale;
    const float4* sh4 = (const float4*)g_shift;

    for (int kk = 0; kk < 27; kk++) {
        int k = (kk == 0) ? 13 : (kk <= 13 ? kk - 1 : kk);
        int cell = chunk * 27 + k;
        int cnt = g_cnt[cell];
        if (cnt == 0) continue;

        __syncthreads();  // prev tap done with Wsm reads + global RMW ordering
        // stage W[k]: 64x64 floats = 1024 float4
        const float4* wsrc = (const float4*)(Wg + ((size_t)cidx * 27 + k) * 4096);
#pragma unroll
        for (int i = 0; i < 4; i++)
            ((float4*)&Wsm[0][0])[tid + i * 256] = wsrc[tid + i * 256];

        int off = cell * CHUNK;
        for (int t0 = 0; t0 < cnt; t0 += TE) {
            int n = min(TE, cnt - t0);
            __syncthreads();  // prev tile GEMM done reading Xs; W staged
            // ---- gather + fused bnrelu into Xs ----
            if (ge < n) {
                int srcp = g_src[off + t0 + ge];
                const float4* row = in4 + (size_t)srcp * 16 + part * 8;
#pragma unroll
                for (int j = 0; j < 8; j++) {
                    float4 v = row[j];
                    float4 sc = sc4[part * 8 + j];
                    float4 sh = sh4[part * 8 + j];
                    int ci = part * 32 + j * 4;
                    Xs[ci + 0][ge] = fmaxf(v.x * sc.x + sh.x, 0.f);
                    Xs[ci + 1][ge] = fmaxf(v.y * sc.y + sh.y, 0.f);
                    Xs[ci + 2][ge] = fmaxf(v.z * sc.z + sh.z, 0.f);
                    Xs[ci + 3][ge] = fmaxf(v.w * sc.w + sh.w, 0.f);
                }
            }
            __syncthreads();
            // ---- GEMM: 4 entry-pairs x 4 oc per thread, fma.rn.f32x2 ----
            unsigned long long acc[4][4];
#pragma unroll
            for (int r = 0; r < 4; r++)
#pragma unroll
                for (int j = 0; j < 4; j++) acc[r][j] = 0ull;
#pragma unroll
            for (int ci = 0; ci < 64; ci++) {
                float4 w = WsV[ci * 16 + tx];
                unsigned long long bw0 = splat2(w.x);
                unsigned long long bw1 = splat2(w.y);
                unsigned long long bw2 = splat2(w.z);
                unsigned long long bw3 = splat2(w.w);
                ulonglong2 xa = XsP[ci * 32 + ty];        // entries 4ty..4ty+3
                ulonglong2 xb = XsP[ci * 32 + 16 + ty];   // entries 64+4ty..
                fma2(acc[0][0], xa.x, bw0); fma2(acc[0][1], xa.x, bw1);
                fma2(acc[0][2], xa.x, bw2); fma2(acc[0][3], xa.x, bw3);
                fma2(acc[1][0], xa.y, bw0); fma2(acc[1][1], xa.y, bw1);
                fma2(acc[1][2], xa.y, bw2); fma2(acc[1][3], xa.y, bw3);
                fma2(acc[2][0], xb.x, bw0); fma2(acc[2][1], xb.x, bw1);
                fma2(acc[2][2], xb.x, bw2); fma2(acc[2][3], xb.x, bw3);
                fma2(acc[3][0], xb.y, bw0); fma2(acc[3][1], xb.y, bw1);
                fma2(acc[3][2], xb.y, bw2); fma2(acc[3][3], xb.y, bw3);
            }
            // ---- scatter(-add) epilogue ----
#pragma unroll
            for (int g = 0; g < 2; g++) {
#pragma unroll
                for (int r = 0; r < 4; r++) {
                    int e = g * 64 + ty * 4 + r;
                    if (e < n) {
                        int r2 = g * 2 + (r >> 1);
                        int hi = r & 1;
                        float2 p0 = unpack2(acc[r2][0]);
                        float2 p1 = unpack2(acc[r2][1]);
                        float2 p2 = unpack2(acc[r2][2]);
                        float2 p3 = unpack2(acc[r2][3]);
                        float4 v = hi ? make_float4(p0.y, p1.y, p2.y, p3.y)
                                      : make_float4(p0.x, p1.x, p2.x, p3.x);
                        int dstp = g_dst[off + t0 + e];
                        float4* orow = (float4*)(out + (size_t)dstp * 64) + tx;
                        if (kk == 0) {
                            if (base) {
                                float4 b4 = ((const float4*)(base + (size_t)dstp * 64))[tx];
                                v.x += b4.x; v.y += b4.y; v.z += b4.z; v.w += b4.w;
                            }
                            *orow = v;
                        } else {
                            float4 o = *orow;
                            o.x += v.x; o.y += v.y; o.z += v.z; o.w += v.w;
                            *orow = o;
                        }
                    }
                }
            }
        }
    }
}

// ---------------- driver (kernel launches only — capture-safe) ----------------
static void run_stage(const float* in_ext, int in_sel,
                      const float* Ws, const float* gammas, const float* betas, int cidx,
                      float* out_ext, int out_sel,
                      const float* base_ext, int base_sel) {
    stats_kernel<<<STATS_BLOCKS, 256>>>(in_ext, in_sel);
    finalize_kernel<<<1, 64>>>(gammas, betas, cidx);
    conv_kernel<<<NCHUNKS, 256>>>(cidx, Ws, in_ext, in_sel, out_ext, out_sel, base_ext, base_sel);
}

extern "C" void kernel_launch(void* const* d_in, const int* in_sizes, int n_in,
                              void* d_out, int out_size) {
    const float* feats  = (const float*)d_in[0];
    const float* Ws     = (const float*)d_in[1];
    const float* gammas = (const float*)d_in[2];
    const float* betas  = (const float*)d_in[3];
    const int*   pos    = (const int*)d_in[4];
    float* outp = (float*)d_out;

    clear_kernel<<<(BB * D3 + 255) / 256, 256>>>();
    scatter_kernel<<<(PP + 255) / 256, 256>>>(pos);
    build_kernel<<<(PP + 255) / 256, 256>>>(pos);

    // block 1: c = conv(bnrelu(feats), W0); x = feats + conv(bnrelu(c), W1)
    run_stage(feats,   0, Ws, gammas, betas, 0, nullptr, 2, nullptr, -1);
    run_stage(nullptr, 2, Ws, gammas, betas, 1, nullptr, 3, feats,    0);
    // block 2: c = conv(bnrelu(x), W2); out = x + conv(bnrelu(c), W3)
    run_stage(nullptr, 3, Ws, gammas, betas, 2, nullptr, 2, nullptr, -1);
    run_stage(nullptr, 2, Ws, gammas, betas, 3, outp,    0, nullptr,  3);
}

// round 10
// speedup vs baseline: 2.0111x; 1.0912x over previous
#include <cuda_runtime.h>
#include <cstdint>

#define BB 2
#define NN 150000
#define CC 64
#define DD 128
#define D3 (DD*DD*DD)
#define PP (BB*NN)                     // 300000 total points
#define CHUNK 1024
#define NCHUNKS ((PP + CHUNK - 1) / CHUNK)   // 293
#define NCELLS (NCHUNKS * 27)
#define TE 128                         // entries per GEMM tile
#define TILEMAX 224
#define STATS_BLOCKS 592
#define BN_EPS 1e-4f

// dynamic smem layout for conv (bytes)
#define XS_OFF   0                      // 2 x 64 x 128 floats = 65536
#define W_OFF    65536                  // 64 x 64 floats = 16384
#define SC_OFF   81920                  // scale 64 + shift 64 floats = 512
#define LIST_OFF 82432                  // 3 x 224 ints = 2688
#define META_OFF 85120                  // 2 ints
#define SMEM_CONV 85376

// ---------------- static device scratch ----------------
__device__ int    g_lut[BB * D3];
__device__ int    g_cnt[NCELLS];
__device__ int    g_dst[NCELLS * CHUNK];
__device__ int    g_src[NCELLS * CHUNK];
__device__ float  g_c[PP * CC];
__device__ float  g_x[PP * CC];
__device__ float  g_ps [STATS_BLOCKS * CC];
__device__ float  g_pss[STATS_BLOCKS * CC];
__device__ __align__(16) float g_scale[CC];
__device__ __align__(16) float g_shift[CC];

// buffer selectors: 0 = external pointer, 2 = g_c, 3 = g_x
__device__ __forceinline__ const float* rbuf(int sel, const float* ext) {
    if (sel == 2) return g_c;
    if (sel == 3) return g_x;
    return ext;
}
__device__ __forceinline__ float* wbuf(int sel, float* ext) {
    if (sel == 2) return g_c;
    if (sel == 3) return g_x;
    return ext;
}

// ---------------- packed f32x2 helpers ----------------
__device__ __forceinline__ unsigned long long splat2(float v) {
    unsigned long long r;
    unsigned int u = __float_as_uint(v);
    asm("mov.b64 %0, {%1, %1};" : "=l"(r) : "r"(u));
    return r;
}
__device__ __forceinline__ void fma2(unsigned long long& d, unsigned long long a, unsigned long long b) {
    asm("fma.rn.f32x2 %0, %1, %2, %0;" : "+l"(d) : "l"(a), "l"(b));
}
__device__ __forceinline__ float2 unpack2(unsigned long long v) {
    float2 r;
    asm("mov.b64 {%0, %1}, %2;" : "=f"(r.x), "=f"(r.y) : "l"(v));
    return r;
}

// ---------------- clear LUT + counters ----------------
__global__ void clear_kernel() {
    int i = blockIdx.x * blockDim.x + threadIdx.x;
    if (i < BB * D3) g_lut[i] = -1;
    if (i < NCELLS)  g_cnt[i] = 0;
}

// ---------------- LUT scatter ----------------
__global__ void scatter_kernel(const int* __restrict__ pos) {
    int p = blockIdx.x * blockDim.x + threadIdx.x;
    if (p >= PP) return;
    int b = p / NN;
    int i = p - b * NN;
    const int* pp = pos + (size_t)p * 3;
    int code = (pp[0] * DD + pp[1]) * DD + pp[2];
    g_lut[b * D3 + code] = i;
}

// ---------------- build rule lists (symmetric: probe 13 taps, emit both dirs) ----------------
__global__ void build_kernel(const int* __restrict__ pos) {
    int p = blockIdx.x * blockDim.x + threadIdx.x;
    if (p >= PP) return;
    int b = p / NN;
    const int* pp = pos + (size_t)p * 3;
    int x = pp[0], y = pp[1], z = pp[2];
    int chunk = p >> 10;
    const int* lut = g_lut + b * D3;
    {   // center tap (13): src = dst = p
        int cell = chunk * 27 + 13;
        int slot = atomicAdd(&g_cnt[cell], 1);
        g_dst[cell * CHUNK + slot] = p;
        g_src[cell * CHUNK + slot] = p;
    }
#pragma unroll
    for (int k = 0; k < 13; k++) {
        int dx = k / 9 - 1, dy = (k / 3) % 3 - 1, dz = k % 3 - 1;
        int nx = x + dx, ny = y + dy, nz = z + dz;
        if ((unsigned)nx < DD && (unsigned)ny < DD && (unsigned)nz < DD) {
            int nidx = lut[(nx * DD + ny) * DD + nz];
            if (nidx >= 0) {
                int qg = b * NN + nidx;
                int cell1 = chunk * 27 + k;
                int s1 = atomicAdd(&g_cnt[cell1], 1);
                g_dst[cell1 * CHUNK + s1] = p;
                g_src[cell1 * CHUNK + s1] = qg;
                int cell2 = (qg >> 10) * 27 + (26 - k);
                int s2 = atomicAdd(&g_cnt[cell2], 1);
                g_dst[cell2 * CHUNK + s2] = qg;
                g_src[cell2 * CHUNK + s2] = p;
            }
        }
    }
}

// ---------------- BN stats for external input (feats) ----------------
__global__ void stats_kernel(const float* __restrict__ ext, int sel) {
    const float4* x4 = (const float4*)rbuf(sel, ext);
    __shared__ float4 ssum[16][16], ssq[16][16];
    int t = threadIdx.x;
    int tx = t & 15;
    int ty = t >> 4;
    float4 s = make_float4(0.f, 0.f, 0.f, 0.f);
    float4 q = make_float4(0.f, 0.f, 0.f, 0.f);
#pragma unroll 4
    for (int row = blockIdx.x * 16 + ty; row < PP; row += gridDim.x * 16) {
        float4 v = x4[(size_t)row * 16 + tx];
        s.x += v.x; s.y += v.y; s.z += v.z; s.w += v.w;
        q.x += v.x * v.x; q.y += v.y * v.y; q.z += v.z * v.z; q.w += v.w * v.w;
    }
    ssum[ty][tx] = s; ssq[ty][tx] = q;
    __syncthreads();
    for (int st = 8; st > 0; st >>= 1) {
        if (ty < st) {
            float4 a = ssum[ty][tx], b = ssum[ty + st][tx];
            a.x += b.x; a.y += b.y; a.z += b.z; a.w += b.w;
            ssum[ty][tx] = a;
            float4 c = ssq[ty][tx], d = ssq[ty + st][tx];
            c.x += d.x; c.y += d.y; c.z += d.z; c.w += d.w;
            ssq[ty][tx] = c;
        }
        __syncthreads();
    }
    if (ty == 0) {
        ((float4*)g_ps )[blockIdx.x * 16 + tx] = ssum[0][tx];
        ((float4*)g_pss)[blockIdx.x * 16 + tx] = ssq[0][tx];
    }
}

__global__ void finalize_kernel(const float* __restrict__ gammas, const float* __restrict__ betas,
                                int cidx, int nb) {
    int ch = threadIdx.x;  // 64 threads
    float s = 0.f, q = 0.f;
    for (int b2 = 0; b2 < nb; b2++) {
        s += g_ps [b2 * 64 + ch];
        q += g_pss[b2 * 64 + ch];
    }
    float inv = 1.0f / (float)PP;
    float mu  = s * inv;
    float var = q * inv - mu * mu;
    float sc  = gammas[cidx * 64 + ch] * rsqrtf(var + BN_EPS);
    g_scale[ch] = sc;
    g_shift[ch] = betas[cidx * 64 + ch] - mu * sc;
}

// ---------------- sparse conv: pipelined register-blocked GEMM (f32x2) ----------------
// One block per 1024-dst chunk. Flat tile schedule over taps (center first, 8 full
// tiles, then 26 taps). Double-buffered Xs; next tile's gather prefetched into regs
// during GEMM. Center tiles: out = base + y (store). Others: out += y.
// Deterministic: tap order fixed, per-entry K-order fixed, block owns its dsts.
// Optional fused stats: block emits per-chunk BN partials of its output rows.
__global__ __launch_bounds__(256, 2) void conv_kernel(int cidx, const float* __restrict__ Wg,
                                                      const float* __restrict__ in_ext, int in_sel,
                                                      float* __restrict__ out_ext, int out_sel,
                                                      const float* __restrict__ base_ext, int base_sel,
                                                      int doStats) {
    extern __shared__ char sm[];
    float*  XsF   = (float*)(sm + XS_OFF);
    float4* Wsm4  = (float4*)(sm + W_OFF);
    float*  sSc   = (float*)(sm + SC_OFF);
    float*  sSh   = sSc + 64;
    int*    sTap  = (int*)(sm + LIST_OFF);
    int*    sOffA = sTap + TILEMAX;
    int*    sNA   = sOffA + TILEMAX;
    int*    sMeta = (int*)(sm + META_OFF);

    const float* in   = rbuf(in_sel, in_ext);
    float* out        = wbuf(out_sel, out_ext);
    const float* base = (base_sel < 0) ? nullptr : rbuf(base_sel, base_ext);
    const float4* in4 = (const float4*)in;
    const float4* Wg4 = (const float4*)Wg;

    int tid  = threadIdx.x;
    int tx   = tid & 15;          // oc group (4 oc)
    int ty   = tid >> 4;          // entry group
    int ge   = tid >> 1;          // gather entry 0..127
    int part = tid & 1;           // gather half (ci 0..31 / 32..63)
    int chunk = blockIdx.x;

    // stage scale/shift
    if (tid < 16) {
        ((float4*)sSc)[tid] = ((const float4*)g_scale)[tid];
        ((float4*)sSh)[tid] = ((const float4*)g_shift)[tid];
    }
    // build flat tile list (warp 0): center tap first
    if (tid < 32) {
        int lane = tid;
        int k = 13, cnt = 0, ntile = 0;
        if (lane < 27) {
            k = (lane == 0) ? 13 : (lane <= 13 ? lane - 1 : lane);
            cnt = g_cnt[chunk * 27 + k];
            ntile = (cnt + TE - 1) >> 7;
        }
        int pfx = ntile;
        for (int d = 1; d < 32; d <<= 1) {
            int v = __shfl_up_sync(0xffffffffu, pfx, d);
            if (lane >= d) pfx += v;
        }
        pfx -= ntile;  // exclusive
        for (int i = 0; i < ntile; i++) {
            sTap[pfx + i]  = k;
            sOffA[pfx + i] = i << 7;
            sNA[pfx + i]   = min(TE, cnt - (i << 7));
        }
        if (lane == 26) sMeta[0] = pfx + ntile;   // total tiles
        if (lane == 0)  sMeta[1] = ntile;         // center tiles
    }
    __syncthreads();

    int nTiles  = sMeta[0];
    int nCenter = sMeta[1];

    // prologue prefetch tile 0
    float4 pf[8];
    int k_cur = 13, n_cur = 0, gb_cur = 0;
    bool wch_cur = true;
    if (nTiles > 0) {
        k_cur = sTap[0]; n_cur = sNA[0];
        gb_cur = (chunk * 27 + k_cur) * CHUNK + sOffA[0];
        if (ge < n_cur) {
            int sp = g_src[gb_cur + ge];
            const float4* row = in4 + (size_t)sp * 16 + part * 8;
#pragma unroll
            for (int j = 0; j < 8; j++) pf[j] = row[j];
        }
    }

    for (int t = 0; t < nTiles; t++) {
        int  kT  = k_cur, nT_e = n_cur, gbT = gb_cur;
        bool wchT = wch_cur;
        __syncthreads();   // phase 1: commit
        float4 wtmp[4];
        if (wchT) {
            const float4* wsrc = Wg4 + ((size_t)cidx * 27 + kT) * 1024;
#pragma unroll
            for (int i = 0; i < 4; i++) wtmp[i] = wsrc[tid + i * 256];
        }
        float* Xb = XsF + (t & 1) * 8192;
        if (ge < nT_e) {
#pragma unroll
            for (int j = 0; j < 8; j++) {
                float4 v = pf[j];
                int ci = part * 32 + j * 4;
                float4 sc = ((const float4*)sSc)[part * 8 + j];
                float4 sh = ((const float4*)sSh)[part * 8 + j];
                Xb[(ci + 0) * TE + ge] = fmaxf(v.x * sc.x + sh.x, 0.f);
                Xb[(ci + 1) * TE + ge] = fmaxf(v.y * sc.y + sh.y, 0.f);
                Xb[(ci + 2) * TE + ge] = fmaxf(v.z * sc.z + sh.z, 0.f);
                Xb[(ci + 3) * TE + ge] = fmaxf(v.w * sc.w + sh.w, 0.f);
            }
        }
        if (wchT) {
#pragma unroll
            for (int i = 0; i < 4; i++) Wsm4[tid + i * 256] = wtmp[i];
        }
        __syncthreads();   // phase 2: prefetch next + GEMM + epilogue
        int tn = t + 1;
        if (tn < nTiles) {
            int k2 = sTap[tn];
            wch_cur = (k2 != kT);
            k_cur = k2; n_cur = sNA[tn];
            gb_cur = (chunk * 27 + k2) * CHUNK + sOffA[tn];
            if (ge < n_cur) {
                int sp = g_src[gb_cur + ge];
                const float4* row = in4 + (size_t)sp * 16 + part * 8;
#pragma unroll
                for (int j = 0; j < 8; j++) pf[j] = row[j];
            }
        }
        // ---- GEMM: 4 entry-pairs x 4 oc per thread, fma.rn.f32x2 ----
        const ulonglong2* XsP = (const ulonglong2*)Xb;
        unsigned long long acc[4][4];
#pragma unroll
        for (int r = 0; r < 4; r++)
#pragma unroll
            for (int j = 0; j < 4; j++) acc[r][j] = 0ull;
#pragma unroll
        for (int ci = 0; ci < 64; ci++) {
            float4 w = Wsm4[ci * 16 + tx];
            unsigned long long bw0 = splat2(w.x);
            unsigned long long bw1 = splat2(w.y);
            unsigned long long bw2 = splat2(w.z);
            unsigned long long bw3 = splat2(w.w);
            ulonglong2 xa = XsP[ci * 32 + ty];
            ulonglong2 xb = XsP[ci * 32 + 16 + ty];
            fma2(acc[0][0], xa.x, bw0); fma2(acc[0][1], xa.x, bw1);
            fma2(acc[0][2], xa.x, bw2); fma2(acc[0][3], xa.x, bw3);
            fma2(acc[1][0], xa.y, bw0); fma2(acc[1][1], xa.y, bw1);
            fma2(acc[1][2], xa.y, bw2); fma2(acc[1][3], xa.y, bw3);
            fma2(acc[2][0], xb.x, bw0); fma2(acc[2][1], xb.x, bw1);
            fma2(acc[2][2], xb.x, bw2); fma2(acc[2][3], xb.x, bw3);
            fma2(acc[3][0], xb.y, bw0); fma2(acc[3][1], xb.y, bw1);
            fma2(acc[3][2], xb.y, bw2); fma2(acc[3][3], xb.y, bw3);
        }
        // ---- epilogue ----
        bool isC = (t < nCenter);
#pragma unroll
        for (int g = 0; g < 2; g++) {
#pragma unroll
            for (int r = 0; r < 4; r++) {
                int e = g * 64 + ty * 4 + r;
                if (e < nT_e) {
                    int r2 = g * 2 + (r >> 1);
                    int hi = r & 1;
                    float2 p0 = unpack2(acc[r2][0]);
                    float2 p1 = unpack2(acc[r2][1]);
                    float2 p2 = unpack2(acc[r2][2]);
                    float2 p3 = unpack2(acc[r2][3]);
                    float4 v = hi ? make_float4(p0.y, p1.y, p2.y, p3.y)
                                  : make_float4(p0.x, p1.x, p2.x, p3.x);
                    int dstp = g_dst[gbT + e];
                    float4* orow = (float4*)(out + (size_t)dstp * 64) + tx;
                    if (isC) {
                        if (base) {
                            float4 b4 = ((const float4*)(base + (size_t)dstp * 64))[tx];
                            v.x += b4.x; v.y += b4.y; v.z += b4.z; v.w += b4.w;
                        }
                        *orow = v;
                    } else {
                        float4 o = *orow;
                        o.x += v.x; o.y += v.y; o.z += v.z; o.w += v.w;
                        *orow = o;
                    }
                }
            }
        }
    }

    // ---- fused BN stats of this chunk's output rows ----
    __syncthreads();
    if (doStats) {
        int nDst = min(CHUNK, PP - chunk * CHUNK);
        const float4* o4 = (const float4*)out;
        float4 s = make_float4(0.f, 0.f, 0.f, 0.f);
        float4 q = make_float4(0.f, 0.f, 0.f, 0.f);
        for (int r = ty; r < nDst; r += 16) {
            float4 v = o4[((size_t)(chunk * CHUNK + r)) * 16 + tx];
            s.x += v.x; s.y += v.y; s.z += v.z; s.w += v.w;
            q.x += v.x * v.x; q.y += v.y * v.y; q.z += v.z * v.z; q.w += v.w * v.w;
        }
        float4* red = (float4*)sm;   // alias Xs (GEMM done)
        red[ty * 16 + tx] = s;
        red[256 + ty * 16 + tx] = q;
        __syncthreads();
        for (int st = 8; st > 0; st >>= 1) {
            if (ty < st) {
                float4 a = red[ty * 16 + tx], b = red[(ty + st) * 16 + tx];
                a.x += b.x; a.y += b.y; a.z += b.z; a.w += b.w;
                red[ty * 16 + tx] = a;
                float4 c = red[256 + ty * 16 + tx], d = red[256 + (ty + st) * 16 + tx];
                c.x += d.x; c.y += d.y; c.z += d.z; c.w += d.w;
                red[256 + ty * 16 + tx] = c;
            }
            __syncthreads();
        }
        if (ty == 0) {
            ((float4*)g_ps )[chunk * 16 + tx] = red[tx];
            ((float4*)g_pss)[chunk * 16 + tx] = red[256 + tx];
        }
    }
}

// ---------------- driver (kernel launches only — capture-safe) ----------------
extern "C" void kernel_launch(void* const* d_in, const int* in_sizes, int n_in,
                              void* d_out, int out_size) {
    const float* feats  = (const float*)d_in[0];
    const float* Ws     = (const float*)d_in[1];
    const float* gammas = (const float*)d_in[2];
    const float* betas  = (const float*)d_in[3];
    const int*   pos    = (const int*)d_in[4];
    float* outp = (float*)d_out;

    cudaFuncSetAttribute(conv_kernel, cudaFuncAttributeMaxDynamicSharedMemorySize, SMEM_CONV);

    clear_kernel<<<(BB * D3 + 255) / 256, 256>>>();
    scatter_kernel<<<(PP + 255) / 256, 256>>>(pos);
    build_kernel<<<(PP + 255) / 256, 256>>>(pos);

    // stage 0: c = conv(bnrelu(feats), W0)                 [stats of c fused]
    stats_kernel<<<STATS_BLOCKS, 256>>>(feats, 0);
    finalize_kernel<<<1, 64>>>(gammas, betas, 0, STATS_BLOCKS);
    conv_kernel<<<NCHUNKS, 256, SMEM_CONV>>>(0, Ws, feats, 0, nullptr, 2, nullptr, -1, 1);
    // stage 1: x = feats + conv(bnrelu(c), W1)             [stats of x fused]
    finalize_kernel<<<1, 64>>>(gammas, betas, 1, NCHUNKS);
    conv_kernel<<<NCHUNKS, 256, SMEM_CONV>>>(1, Ws, nullptr, 2, nullptr, 3, feats, 0, 1);
    // stage 2: c = conv(bnrelu(x), W2)                     [stats of c fused]
    finalize_kernel<<<1, 64>>>(gammas, betas, 2, NCHUNKS);
    conv_kernel<<<NCHUNKS, 256, SMEM_CONV>>>(2, Ws, nullptr, 3, nullptr, 2, nullptr, -1, 1);
    // stage 3: out = x + conv(bnrelu(c), W3)
    finalize_kernel<<<1, 64>>>(gammas, betas, 3, NCHUNKS);
    conv_kernel<<<NCHUNKS, 256, SMEM_CONV>>>(3, Ws, nullptr, 2, outp, 0, nullptr, 3, 0);
}

// round 14
// speedup vs baseline: 2.0168x; 1.0029x over previous
#include <cuda_runtime.h>
#include <cstdint>

#define BB 2
#define NN 150000
#define CC 64
#define DD 128
#define D3 (DD*DD*DD)
#define PP (BB*NN)                     // 300000 total points
#define CHUNK 1024
#define NCHUNKS ((PP + CHUNK - 1) / CHUNK)   // 293
#define NCELLS (NCHUNKS * 27)
#define TE 128                         // entries per GEMM tile
#define TILEMAX 224
#define STATS_BLOCKS 592
#define BN_EPS 1e-4f

// dynamic smem layout for conv (bytes)
#define XS_OFF   0                      // 2 x 64 x 128 floats = 65536
#define W_OFF    65536                  // 64 x 64 floats = 16384
#define SC_OFF   81920                  // scale 64 + shift 64 floats = 512
#define LIST_OFF 82432                  // 3 x 224 ints = 2688
#define META_OFF 85120                  // 2 ints
#define SMEM_CONV 85376

// ---------------- static device scratch ----------------
__device__ int    g_lut[BB * D3];
__device__ int    g_cnt[NCELLS];
__device__ int    g_dst[NCELLS * CHUNK];
__device__ int    g_src[NCELLS * CHUNK];
__device__ float  g_c[PP * CC];
__device__ float  g_x[PP * CC];
__device__ float  g_ps [STATS_BLOCKS * CC];
__device__ float  g_pss[STATS_BLOCKS * CC];
__device__ __align__(16) float g_scale[CC];
__device__ __align__(16) float g_shift[CC];

// buffer selectors: 0 = external pointer, 2 = g_c, 3 = g_x
__device__ __forceinline__ const float* rbuf(int sel, const float* ext) {
    if (sel == 2) return g_c;
    if (sel == 3) return g_x;
    return ext;
}
__device__ __forceinline__ float* wbuf(int sel, float* ext) {
    if (sel == 2) return g_c;
    if (sel == 3) return g_x;
    return ext;
}

// ---------------- packed f32x2 helpers ----------------
__device__ __forceinline__ unsigned long long splat2(float v) {
    unsigned long long r;
    unsigned int u = __float_as_uint(v);
    asm("mov.b64 %0, {%1, %1};" : "=l"(r) : "r"(u));
    return r;
}
__device__ __forceinline__ void fma2(unsigned long long& d, unsigned long long a, unsigned long long b) {
    asm("fma.rn.f32x2 %0, %1, %2, %0;" : "+l"(d) : "l"(a), "l"(b));
}
__device__ __forceinline__ float2 unpack2(unsigned long long v) {
    float2 r;
    asm("mov.b64 {%0, %1}, %2;" : "=f"(r.x), "=f"(r.y) : "l"(v));
    return r;
}

// ---------------- clear LUT + counters ----------------
__global__ void clear_kernel() {
    int i = blockIdx.x * blockDim.x + threadIdx.x;
    if (i < BB * D3) g_lut[i] = -1;
    if (i < NCELLS)  g_cnt[i] = 0;
}

// ---------------- LUT scatter ----------------
__global__ void scatter_kernel(const int* __restrict__ pos) {
    int p = blockIdx.x * blockDim.x + threadIdx.x;
    if (p >= PP) return;
    int b = p / NN;
    int i = p - b * NN;
    const int* pp = pos + (size_t)p * 3;
    int code = (pp[0] * DD + pp[1]) * DD + pp[2];
    g_lut[b * D3 + code] = i;
}

// ---------------- build rule lists (symmetric: probe 13 taps, emit both dirs) ----------------
__global__ void build_kernel(const int* __restrict__ pos) {
    int p = blockIdx.x * blockDim.x + threadIdx.x;
    if (p >= PP) return;
    int b = p / NN;
    const int* pp = pos + (size_t)p * 3;
    int x = pp[0], y = pp[1], z = pp[2];
    int chunk = p >> 10;
    const int* lut = g_lut + b * D3;
    {   // center tap (13): src = dst = p
        int cell = chunk * 27 + 13;
        int slot = atomicAdd(&g_cnt[cell], 1);
        g_dst[cell * CHUNK + slot] = p;
        g_src[cell * CHUNK + slot] = p;
    }
#pragma unroll
    for (int k = 0; k < 13; k++) {
        int dx = k / 9 - 1, dy = (k / 3) % 3 - 1, dz = k % 3 - 1;
        int nx = x + dx, ny = y + dy, nz = z + dz;
        if ((unsigned)nx < DD && (unsigned)ny < DD && (unsigned)nz < DD) {
            int nidx = lut[(nx * DD + ny) * DD + nz];
            if (nidx >= 0) {
                int qg = b * NN + nidx;
                int cell1 = chunk * 27 + k;
                int s1 = atomicAdd(&g_cnt[cell1], 1);
                g_dst[cell1 * CHUNK + s1] = p;
                g_src[cell1 * CHUNK + s1] = qg;
                int cell2 = (qg >> 10) * 27 + (26 - k);
                int s2 = atomicAdd(&g_cnt[cell2], 1);
                g_dst[cell2 * CHUNK + s2] = qg;
                g_src[cell2 * CHUNK + s2] = p;
            }
        }
    }
}

// ---------------- BN stats for external input (feats) ----------------
__global__ void stats_kernel(const float* __restrict__ ext, int sel) {
    const float4* x4 = (const float4*)rbuf(sel, ext);
    __shared__ float4 ssum[16][16], ssq[16][16];
    int t = threadIdx.x;
    int tx = t & 15;
    int ty = t >> 4;
    float4 s = make_float4(0.f, 0.f, 0.f, 0.f);
    float4 q = make_float4(0.f, 0.f, 0.f, 0.f);
#pragma unroll 4
    for (int row = blockIdx.x * 16 + ty; row < PP; row += gridDim.x * 16) {
        float4 v = x4[(size_t)row * 16 + tx];
        s.x += v.x; s.y += v.y; s.z += v.z; s.w += v.w;
        q.x += v.x * v.x; q.y += v.y * v.y; q.z += v.z * v.z; q.w += v.w * v.w;
    }
    ssum[ty][tx] = s; ssq[ty][tx] = q;
    __syncthreads();
    for (int st = 8; st > 0; st >>= 1) {
        if (ty < st) {
            float4 a = ssum[ty][tx], b = ssum[ty + st][tx];
            a.x += b.x; a.y += b.y; a.z += b.z; a.w += b.w;
            ssum[ty][tx] = a;
            float4 c = ssq[ty][tx], d = ssq[ty + st][tx];
            c.x += d.x; c.y += d.y; c.z += d.z; c.w += d.w;
            ssq[ty][tx] = c;
        }
        __syncthreads();
    }
    if (ty == 0) {
        ((float4*)g_ps )[blockIdx.x * 16 + tx] = ssum[0][tx];
        ((float4*)g_pss)[blockIdx.x * 16 + tx] = ssq[0][tx];
    }
}

__global__ void finalize_kernel(const float* __restrict__ gammas, const float* __restrict__ betas,
                                int cidx, int nb) {
    int ch = threadIdx.x;  // 64 threads
    float s = 0.f, q = 0.f;
    for (int b2 = 0; b2 < nb; b2++) {
        s += g_ps [b2 * 64 + ch];
        q += g_pss[b2 * 64 + ch];
    }
    float inv = 1.0f / (float)PP;
    float mu  = s * inv;
    float var = q * inv - mu * mu;
    float sc  = gammas[cidx * 64 + ch] * rsqrtf(var + BN_EPS);
    g_scale[ch] = sc;
    g_shift[ch] = betas[cidx * 64 + ch] - mu * sc;
}

// ---------------- sparse conv: pipelined register-blocked GEMM (f32x2) ----------------
// One block per 1024-dst chunk. Flat tile schedule over taps (center first).
// Double-buffered Xs; BOTH next tile's gather AND its W slice are prefetched into
// registers during the GEMM phase, so phase 1 is pure STS (no exposed LDG latency).
// Center tiles: out = base + y (store). Others: out += y.
// Deterministic: tap order fixed, per-entry K-order fixed, block owns its dsts.
// Optional fused stats: block emits per-chunk BN partials of its output rows.
__global__ __launch_bounds__(256, 2) void conv_kernel(int cidx, const float* __restrict__ Wg,
                                                      const float* __restrict__ in_ext, int in_sel,
                                                      float* __restrict__ out_ext, int out_sel,
                                                      const float* __restrict__ base_ext, int base_sel,
                                                      int doStats) {
    extern __shared__ char sm[];
    float*  XsF   = (float*)(sm + XS_OFF);
    float4* Wsm4  = (float4*)(sm + W_OFF);
    float*  sSc   = (float*)(sm + SC_OFF);
    float*  sSh   = sSc + 64;
    int*    sTap  = (int*)(sm + LIST_OFF);
    int*    sOffA = sTap + TILEMAX;
    int*    sNA   = sOffA + TILEMAX;
    int*    sMeta = (int*)(sm + META_OFF);

    const float* in   = rbuf(in_sel, in_ext);
    float* out        = wbuf(out_sel, out_ext);
    const float* base = (base_sel < 0) ? nullptr : rbuf(base_sel, base_ext);
    const float4* in4 = (const float4*)in;
    const float4* Wg4 = (const float4*)Wg;

    int tid  = threadIdx.x;
    int tx   = tid & 15;          // oc group (4 oc)
    int ty   = tid >> 4;          // entry group
    int ge   = tid >> 1;          // gather entry 0..127
    int part = tid & 1;           // gather half (ci 0..31 / 32..63)
    int chunk = blockIdx.x;

    // stage scale/shift
    if (tid < 16) {
        ((float4*)sSc)[tid] = ((const float4*)g_scale)[tid];
        ((float4*)sSh)[tid] = ((const float4*)g_shift)[tid];
    }
    // build flat tile list (warp 0): center tap first
    if (tid < 32) {
        int lane = tid;
        int k = 13, cnt = 0, ntile = 0;
        if (lane < 27) {
            k = (lane == 0) ? 13 : (lane <= 13 ? lane - 1 : lane);
            cnt = g_cnt[chunk * 27 + k];
            ntile = (cnt + TE - 1) >> 7;
        }
        int pfx = ntile;
        for (int d = 1; d < 32; d <<= 1) {
            int v = __shfl_up_sync(0xffffffffu, pfx, d);
            if (lane >= d) pfx += v;
        }
        pfx -= ntile;  // exclusive
        for (int i = 0; i < ntile; i++) {
            sTap[pfx + i]  = k;
            sOffA[pfx + i] = i << 7;
            sNA[pfx + i]   = min(TE, cnt - (i << 7));
        }
        if (lane == 26) sMeta[0] = pfx + ntile;   // total tiles
        if (lane == 0)  sMeta[1] = ntile;         // center tiles
    }
    __syncthreads();

    int nTiles  = sMeta[0];
    int nCenter = sMeta[1];

    // prologue prefetch tile 0 (X rows + W slice)
    float4 pf[8];
    float4 wpf[4];
    int k_cur = 13, n_cur = 0, gb_cur = 0;
    bool wch_cur = true;
    if (nTiles > 0) {
        k_cur = sTap[0]; n_cur = sNA[0];
        gb_cur = (chunk * 27 + k_cur) * CHUNK + sOffA[0];
        if (ge < n_cur) {
            int sp = g_src[gb_cur + ge];
            const float4* row = in4 + (size_t)sp * 16 + part * 8;
#pragma unroll
            for (int j = 0; j < 8; j++) pf[j] = row[j];
        }
        const float4* wsrc = Wg4 + ((size_t)cidx * 27 + k_cur) * 1024;
#pragma unroll
        for (int i = 0; i < 4; i++) wpf[i] = wsrc[tid + i * 256];
    }

    for (int t = 0; t < nTiles; t++) {
        int  kT  = k_cur, nT_e = n_cur, gbT = gb_cur;
        bool wchT = wch_cur;
        __syncthreads();   // phase 1: commit (pure STS — no LDG latency here)
        float* Xb = XsF + (t & 1) * 8192;
        if (ge < nT_e) {
#pragma unroll
            for (int j = 0; j < 8; j++) {
                float4 v = pf[j];
                int ci = part * 32 + j * 4;
                float4 sc = ((const float4*)sSc)[part * 8 + j];
                float4 sh = ((const float4*)sSh)[part * 8 + j];
                Xb[(ci + 0) * TE + ge] = fmaxf(v.x * sc.x + sh.x, 0.f);
                Xb[(ci + 1) * TE + ge] = fmaxf(v.y * sc.y + sh.y, 0.f);
                Xb[(ci + 2) * TE + ge] = fmaxf(v.z * sc.z + sh.z, 0.f);
                Xb[(ci + 3) * TE + ge] = fmaxf(v.w * sc.w + sh.w, 0.f);
            }
        }
        if (wchT) {
#pragma unroll
            for (int i = 0; i < 4; i++) Wsm4[tid + i * 256] = wpf[i];
        }
        __syncthreads();   // phase 2: prefetch next (X + W) + GEMM + epilogue
        int tn = t + 1;
        if (tn < nTiles) {
            int k2 = sTap[tn];
            wch_cur = (k2 != kT);
            k_cur = k2; n_cur = sNA[tn];
            gb_cur = (chunk * 27 + k2) * CHUNK + sOffA[tn];
            if (ge < n_cur) {
                int sp = g_src[gb_cur + ge];
                const float4* row = in4 + (size_t)sp * 16 + part * 8;
#pragma unroll
                for (int j = 0; j < 8; j++) pf[j] = row[j];
            }
            if (wch_cur) {
                const float4* wsrc = Wg4 + ((size_t)cidx * 27 + k2) * 1024;
#pragma unroll
                for (int i = 0; i < 4; i++) wpf[i] = wsrc[tid + i * 256];
            }
        }
        // ---- GEMM: 4 entry-pairs x 4 oc per thread, fma.rn.f32x2 ----
        const ulonglong2* XsP = (const ulonglong2*)Xb;
        unsigned long long acc[4][4];
#pragma unroll
        for (int r = 0; r < 4; r++)
#pragma unroll
            for (int j = 0; j < 4; j++) acc[r][j] = 0ull;
#pragma unroll
        for (int ci = 0; ci < 64; ci++) {
            float4 w = Wsm4[ci * 16 + tx];
            unsigned long long bw0 = splat2(w.x);
            unsigned long long bw1 = splat2(w.y);
            unsigned long long bw2 = splat2(w.z);
            unsigned long long bw3 = splat2(w.w);
            ulonglong2 xa = XsP[ci * 32 + ty];
            ulonglong2 xb = XsP[ci * 32 + 16 + ty];
            fma2(acc[0][0], xa.x, bw0); fma2(acc[0][1], xa.x, bw1);
            fma2(acc[0][2], xa.x, bw2); fma2(acc[0][3], xa.x, bw3);
            fma2(acc[1][0], xa.y, bw0); fma2(acc[1][1], xa.y, bw1);
            fma2(acc[1][2], xa.y, bw2); fma2(acc[1][3], xa.y, bw3);
            fma2(acc[2][0], xb.x, bw0); fma2(acc[2][1], xb.x, bw1);
            fma2(acc[2][2], xb.x, bw2); fma2(acc[2][3], xb.x, bw3);
            fma2(acc[3][0], xb.y, bw0); fma2(acc[3][1], xb.y, bw1);
            fma2(acc[3][2], xb.y, bw2); fma2(acc[3][3], xb.y, bw3);
        }
        // ---- epilogue ----
        bool isC = (t < nCenter);
#pragma unroll
        for (int g = 0; g < 2; g++) {
#pragma unroll
            for (int r = 0; r < 4; r++) {
                int e = g * 64 + ty * 4 + r;
                if (e < nT_e) {
                    int r2 = g * 2 + (r >> 1);
                    int hi = r & 1;
                    float2 p0 = unpack2(acc[r2][0]);
                    float2 p1 = unpack2(acc[r2][1]);
                    float2 p2 = unpack2(acc[r2][2]);
                    float2 p3 = unpack2(acc[r2][3]);
                    float4 v = hi ? make_float4(p0.y, p1.y, p2.y, p3.y)
                                  : make_float4(p0.x, p1.x, p2.x, p3.x);
                    int dstp = g_dst[gbT + e];
                    float4* orow = (float4*)(out + (size_t)dstp * 64) + tx;
                    if (isC) {
                        if (base) {
                            float4 b4 = ((const float4*)(base + (size_t)dstp * 64))[tx];
                            v.x += b4.x; v.y += b4.y; v.z += b4.z; v.w += b4.w;
                        }
                        *orow = v;
                    } else {
                        float4 o = *orow;
                        o.x += v.x; o.y += v.y; o.z += v.z; o.w += v.w;
                        *orow = o;
                    }
                }
            }
        }
    }

    // ---- fused BN stats of this chunk's output rows ----
    __syncthreads();
    if (doStats) {
        int nDst = min(CHUNK, PP - chunk * CHUNK);
        const float4* o4 = (const float4*)out;
        float4 s = make_float4(0.f, 0.f, 0.f, 0.f);
        float4 q = make_float4(0.f, 0.f, 0.f, 0.f);
        for (int r = ty; r < nDst; r += 16) {
            float4 v = o4[((size_t)(chunk * CHUNK + r)) * 16 + tx];
            s.x += v.x; s.y += v.y; s.z += v.z; s.w += v.w;
            q.x += v.x * v.x; q.y += v.y * v.y; q.z += v.z * v.z; q.w += v.w * v.w;
        }
        float4* red = (float4*)sm;   // alias Xs (GEMM done)
        red[ty * 16 + tx] = s;
        red[256 + ty * 16 + tx] = q;
        __syncthreads();
        for (int st = 8; st > 0; st >>= 1) {
            if (ty < st) {
                float4 a = red[ty * 16 + tx], b = red[(ty + st) * 16 + tx];
                a.x += b.x; a.y += b.y; a.z += b.z; a.w += b.w;
                red[ty * 16 + tx] = a;
                float4 c = red[256 + ty * 16 + tx], d = red[256 + (ty + st) * 16 + tx];
                c.x += d.x; c.y += d.y; c.z += d.z; c.w += d.w;
                red[256 + ty * 16 + tx] = c;
            }
            __syncthreads();
        }
        if (ty == 0) {
            ((float4*)g_ps )[chunk * 16 + tx] = red[tx];
            ((float4*)g_pss)[chunk * 16 + tx] = red[256 + tx];
        }
    }
}

// ---------------- driver (kernel launches only — capture-safe) ----------------
extern "C" void kernel_launch(void* const* d_in, const int* in_sizes, int n_in,
                              void* d_out, int out_size) {
    const float* feats  = (const float*)d_in[0];
    const float* Ws     = (const float*)d_in[1];
    const float* gammas = (const float*)d_in[2];
    const float* betas  = (const float*)d_in[3];
    const int*   pos    = (const int*)d_in[4];
    float* outp = (float*)d_out;

    cudaFuncSetAttribute(conv_kernel, cudaFuncAttributeMaxDynamicSharedMemorySize, SMEM_CONV);

    clear_kernel<<<(BB * D3 + 255) / 256, 256>>>();
    scatter_kernel<<<(PP + 255) / 256, 256>>>(pos);
    build_kernel<<<(PP + 255) / 256, 256>>>(pos);

    // stage 0: c = conv(bnrelu(feats), W0)                 [stats of c fused]
    stats_kernel<<<STATS_BLOCKS, 256>>>(feats, 0);
    finalize_kernel<<<1, 64>>>(gammas, betas, 0, STATS_BLOCKS);
    conv_kernel<<<NCHUNKS, 256, SMEM_CONV>>>(0, Ws, feats, 0, nullptr, 2, nullptr, -1, 1);
    // stage 1: x = feats + conv(bnrelu(c), W1)             [stats of x fused]
    finalize_kernel<<<1, 64>>>(gammas, betas, 1, NCHUNKS);
    conv_kernel<<<NCHUNKS, 256, SMEM_CONV>>>(1, Ws, nullptr, 2, nullptr, 3, feats, 0, 1);
    // stage 2: c = conv(bnrelu(x), W2)                     [stats of c fused]
    finalize_kernel<<<1, 64>>>(gammas, betas, 2, NCHUNKS);
    conv_kernel<<<NCHUNKS, 256, SMEM_CONV>>>(2, Ws, nullptr, 3, nullptr, 2, nullptr, -1, 1);
    // stage 3: out = x + conv(bnrelu(c), W3)
    finalize_kernel<<<1, 64>>>(gammas, betas, 3, NCHUNKS);
    conv_kernel<<<NCHUNKS, 256, SMEM_CONV>>>(3, Ws, nullptr, 2, outp, 0, nullptr, 3, 0);
}